// round 15
// baseline (speedup 1.0000x reference)
#include <cuda_runtime.h>
#include <cuda_fp16.h>
#include <cstdint>

// Problem constants
#define B_  8
#define N_  1024
#define C_  1024
#define V_  256
#define NK  16        // harmonics 1..16 (k=0 contributes exactly 0)

// Tiling: 128x64 CTA tile, BK=64, 2-stage, 1-pass fp16 MMA (R9 mainloop)
#define TM  128
#define TN  64
#define BK  64
#define NCHUNK (C_/BK)     // 16
#define NRB (B_*N_/TM)     // 64 row blocks
#define NCB (V_/TN)        // 4 col blocks -> grid 256 CTAs, occ 2 -> one wave

// Padded SMEM rows: 64 fp16 = 128B + 16B pad (conflict-free ldmatrix)
#define LDS_ROW 144
#define A_MAT (TM * LDS_ROW)           // 18432
#define B_MAT (TN * LDS_ROW)           // 9216
#define OFF_A  0
#define OFF_B  (A_MAT)
#define STAGE_BYTES (A_MAT + B_MAT)    // 27648
#define XS_LD 68
#define SMEM_DYN (2*STAGE_BYTES)       // 55296 -> 2 CTAs/SM

#define FIN_BLOCKS 64

__device__ __half g_Bt[(size_t)V_*C_];           // A^T in fp16: [v][c]
__device__ float g_part[NRB][V_][2*NK];
__device__ float g_psum[FIN_BLOCKS];
__device__ unsigned int g_done;   // zero-init; reset by last block each run

// ---------------- helpers ----------------
__device__ __forceinline__ uint32_t smem_u32(const void* p) {
    uint32_t a;
    asm("{ .reg .u64 t; cvta.to.shared.u64 t, %1; cvt.u32.u64 %0, t; }" : "=r"(a) : "l"(p));
    return a;
}

__device__ __forceinline__ void ldsm4(uint32_t* r, uint32_t addr) {
    asm volatile("ldmatrix.sync.aligned.m8n8.x4.shared.b16 {%0,%1,%2,%3}, [%4];"
        : "=r"(r[0]), "=r"(r[1]), "=r"(r[2]), "=r"(r[3]) : "r"(addr));
}

__device__ __forceinline__ void mma_f16(float* c, const uint32_t* a, const uint32_t* b) {
    asm volatile(
        "mma.sync.aligned.m16n8k16.row.col.f32.f16.f16.f32 "
        "{%0,%1,%2,%3}, {%4,%5,%6,%7}, {%8,%9}, {%0,%1,%2,%3};"
        : "+f"(c[0]), "+f"(c[1]), "+f"(c[2]), "+f"(c[3])
        : "r"(a[0]), "r"(a[1]), "r"(a[2]), "r"(a[3]), "r"(b[0]), "r"(b[1]));
}

__device__ __forceinline__ void cp_async16(uint32_t dst, const void* src) {
    asm volatile("cp.async.cg.shared.global [%0], [%1], 16;" :: "r"(dst), "l"(src));
}
#define CP_COMMIT() asm volatile("cp.async.commit_group;" ::: "memory")
#define CP_WAIT0()  asm volatile("cp.async.wait_group 0;" ::: "memory")

// ---------------- prep kernel: transpose A (C,V) -> Bt (V,C) fp16 ----------------
__global__ void prep_B(const float* __restrict__ Amat)
{
    __shared__ float sh[32][33];
    const int c0 = blockIdx.x * 32, v0 = blockIdx.y * 32;
    const int tx = threadIdx.x, ty = threadIdx.y;   // 32 x 8
    #pragma unroll
    for (int j = 0; j < 4; j++)
        sh[ty + 8*j][tx] = Amat[(size_t)(c0 + ty + 8*j) * V_ + v0 + tx];
    __syncthreads();
    #pragma unroll
    for (int j = 0; j < 4; j++) {
        const int v = v0 + ty + 8*j, c = c0 + tx;
        g_Bt[(size_t)v * C_ + c] = __float2half_rn(sh[tx][ty + 8*j]);
    }
}

// ---------------- staging ----------------
// A tile: TM x BK = 128x64 fp32 = 2048 float4; 8 per thread
__device__ __forceinline__ void load_A_regs(const float* __restrict__ proj, int row0, int ch, int t, float4* ar)
{
    const float* p = proj + (size_t)(row0 + (t >> 4)) * C_ + ch * BK + (t & 15) * 4;
    #pragma unroll
    for (int j = 0; j < 8; j++)
        ar[j] = *(const float4*)(p + (size_t)16 * j * C_);
}

// convert fp32 -> fp16 and store
__device__ __forceinline__ void store_A(char* stage, int t, const float4* ar)
{
    const int kb = (t & 15) * 8;   // byte offset of 4 fp16
    #pragma unroll
    for (int j = 0; j < 8; j++) {
        const int row = (t >> 4) + 16 * j;
        const int off = row * LDS_ROW + kb;
        float4 a = ar[j];
        __half2 h01 = __floats2half2_rn(a.x, a.y);
        __half2 h23 = __floats2half2_rn(a.z, a.w);
        *(uint2*)(stage + OFF_A + off) = make_uint2(*(uint32_t*)&h01, *(uint32_t*)&h23);
    }
}

// B tile: TN x BK fp16 = 8192B = 512 16B segments; 2 per thread
__device__ __forceinline__ void stage_B_async(uint32_t sg, int col0, int ch, int t)
{
    #pragma unroll
    for (int j = 0; j < 2; j++) {
        const int i = t + 256 * j;
        const int row = i >> 3, kq = i & 7;
        const size_t g = (size_t)(col0 + row) * C_ + ch * BK + kq * 8;
        const uint32_t off = (uint32_t)(row * LDS_ROW + kq * 16);
        cp_async16(sg + OFF_B + off, g_Bt + g);
    }
    CP_COMMIT();
}

// ---------------- main fused kernel (R9 mainloop) ----------------
__global__ void __launch_bounds__(256, 2) gemm_cf_tc(const float* __restrict__ proj)
{
    extern __shared__ char smem[];
    const uint32_t sbase = smem_u32(smem);

    const int tid  = threadIdx.x;
    const int wid  = tid >> 5;
    const int lane = tid & 31;
    const int rb   = blockIdx.x;            // 0..63
    const int cb   = blockIdx.y;            // 0..3
    const int row0 = rb * TM;
    const int col0 = cb * TN;

    // warp grid 4(M) x 2(N): warp tile 32x32
    const int wm0 = (wid >> 1) * 32;
    const int wn0 = (wid & 1) * 32;

    // per-lane ldmatrix address components
    const int sub = lane >> 3, r8 = lane & 7;
    const int a_m = r8 + (sub & 1) * 8;
    const int a_k = (sub >> 1) * 8;
    const int b_n = r8 + (sub >> 1) * 8;
    const int b_k = (sub & 1) * 8;

    float acc[2][4][4];
    #pragma unroll
    for (int mt = 0; mt < 2; mt++)
        #pragma unroll
        for (int nt = 0; nt < 4; nt++)
            #pragma unroll
            for (int j = 0; j < 4; j++) acc[mt][nt][j] = 0.0f;

    float4 ar[8];

    // prologue: fill stage 0
    stage_B_async(sbase, col0, 0, tid);
    load_A_regs(proj, row0, 0, tid, ar);
    store_A(smem, tid, ar);
    CP_WAIT0();
    __syncthreads();

    for (int ch = 0; ch < NCHUNK; ch++) {
        const uint32_t sg = sbase + (ch & 1) * STAGE_BYTES;
        const uint32_t sn = sbase + ((ch + 1) & 1) * STAGE_BYTES;
        char* nxt = smem + ((ch + 1) & 1) * STAGE_BYTES;
        const bool more = (ch + 1 < NCHUNK);

        if (more) {
            stage_B_async(sn, col0, ch + 1, tid);       // async B fill of next buffer
            load_A_regs(proj, row0, ch + 1, tid, ar);   // A LDGs in flight during compute
        }

        // compute on current stage: 4 k-steps
        #pragma unroll
        for (int ks = 0; ks < 4; ks++) {
            const int k0 = ks * 16;
            uint32_t fb[4][2];
            #pragma unroll
            for (int ng = 0; ng < 2; ng++) {
                uint32_t tmp[4];
                const uint32_t baddr = sg + (uint32_t)(OFF_B + (wn0 + ng*16 + b_n) * LDS_ROW + (k0 + b_k) * 2);
                ldsm4(tmp, baddr);
                fb[2*ng][0] = tmp[0]; fb[2*ng][1] = tmp[1];
                fb[2*ng+1][0] = tmp[2]; fb[2*ng+1][1] = tmp[3];
            }
            #pragma unroll
            for (int mt = 0; mt < 2; mt++) {
                uint32_t fa[4];
                const uint32_t aaddr = sg + (uint32_t)(OFF_A + (wm0 + mt*16 + a_m) * LDS_ROW + (k0 + a_k) * 2);
                ldsm4(fa, aaddr);
                #pragma unroll
                for (int nt = 0; nt < 4; nt++)
                    mma_f16(acc[mt][nt], fa, fb[nt]);
            }
        }

        if (more) {
            store_A(nxt, tid, ar);   // next-buffer readers all passed previous barrier
            CP_WAIT0();
            __syncthreads();         // single barrier per chunk
        }
    }

    // ---- epilogue: accumulators -> xs[128][XS_LD] ----
    __syncthreads();   // all MMA reads of final stage done before smem reuse
    float* xs = (float*)smem;
    {
        const int mrow = lane >> 2;
        const int ncol = 2 * (lane & 3);
        #pragma unroll
        for (int mt = 0; mt < 2; mt++)
            #pragma unroll
            for (int nt = 0; nt < 4; nt++) {
                const int m = wm0 + mt*16 + mrow;
                const int n = wn0 + nt*8 + ncol;
                *(float2*)&xs[(size_t)m * XS_LD + n]       = make_float2(acc[mt][nt][0], acc[mt][nt][1]);
                *(float2*)&xs[(size_t)(m + 8) * XS_LD + n] = make_float2(acc[mt][nt][2], acc[mt][nt][3]);
            }
    }
    __syncthreads();

    // ---- trig phase: 4 lanes per column, 32 rows each ----
    const int col = tid >> 2;      // 0..63
    const int q   = tid & 3;       // row quarter
    const float dt = 3.0f / 16.0f;
    float cacc[NK], sacc[NK];
    #pragma unroll
    for (int k = 0; k < NK; k++) { cacc[k] = 0.0f; sacc[k] = 0.0f; }

    #pragma unroll 4
    for (int i = 0; i < 32; i++) {
        float x = xs[(size_t)(q * 32 + i) * XS_LD + col];
        float s1, c1;
        __sincosf(x * dt, &s1, &c1);
        float tc = 2.0f * c1;
        float ckm = 1.0f, skm = 0.0f;
        float ck = c1, sk = s1;
        cacc[0] += c1; sacc[0] += s1;
        #pragma unroll
        for (int k = 1; k < NK; k++) {
            float cn = fmaf(tc, ck, -ckm);
            float sn = fmaf(tc, sk, -skm);
            ckm = ck; skm = sk; ck = cn; sk = sn;
            cacc[k] += cn; sacc[k] += sn;
        }
    }
    #pragma unroll
    for (int k = 0; k < NK; k++) {
        cacc[k] += __shfl_xor_sync(0xffffffffu, cacc[k], 1);
        cacc[k] += __shfl_xor_sync(0xffffffffu, cacc[k], 2);
        sacc[k] += __shfl_xor_sync(0xffffffffu, sacc[k], 1);
        sacc[k] += __shfl_xor_sync(0xffffffffu, sacc[k], 2);
    }
    if (q == 0) {
        float4* dst = (float4*)&g_part[rb][col0 + col][0];
        #pragma unroll
        for (int m = 0; m < NK / 2; m++)
            dst[m] = make_float4(cacc[2*m], sacc[2*m], cacc[2*m+1], sacc[2*m+1]);
    }
}

// ---------------- finalize: 64 blocks; 8 lanes per (b,v) cell ----------------
__global__ void finalize1(float* out)
{
    const int b  = blockIdx.x >> 3;
    const int vg = blockIdx.x & 7;
    const int vl = threadIdx.x >> 3;     // 0..31 (v within group)
    const int m  = threadIdx.x & 7;      // float4 column owner (harmonics 2m, 2m+1)
    const int v  = vg * 32 + vl;

    float4 u = make_float4(0.f, 0.f, 0.f, 0.f);
    #pragma unroll
    for (int j = 0; j < 8; j++) {
        float4 p = *(const float4*)&g_part[b*8 + j][v][m*4];
        u.x += p.x; u.y += p.y; u.z += p.z; u.w += p.w;
    }

    const float dt = 3.0f / 16.0f;
    const float invN = 1.0f / (float)N_;
    float stat = 0.0f;
    {
        int k = 2*m;
        float t = (float)(k + 1) * dt;
        float phi = expf(-0.5f * t * t);
        float w = ((k == NK - 1) ? 1.0f : 2.0f) * dt * phi;
        float cm = u.x * invN, sm = u.y * invN;
        float d = cm - phi;
        stat += (d*d + sm*sm) * w;
        k = 2*m + 1;
        t = (float)(k + 1) * dt;
        phi = expf(-0.5f * t * t);
        w = ((k == NK - 1) ? 1.0f : 2.0f) * dt * phi;
        cm = u.z * invN; sm = u.w * invN;
        d = cm - phi;
        stat += (d*d + sm*sm) * w;
    }
    stat *= (float)N_;

    stat += __shfl_xor_sync(0xffffffffu, stat, 1);
    stat += __shfl_xor_sync(0xffffffffu, stat, 2);
    stat += __shfl_xor_sync(0xffffffffu, stat, 4);

    __shared__ float sh[32];
    __shared__ unsigned int s_last;
    if (m == 0) sh[vl] = stat;
    __syncthreads();

    if (threadIdx.x == 0) {
        float s = 0.0f;
        #pragma unroll
        for (int i = 0; i < 32; i++) s += sh[i];     // fixed order
        g_psum[blockIdx.x] = s;
        __threadfence();
        s_last = atomicAdd(&g_done, 1u);
    }
    __syncthreads();
    if (threadIdx.x == 0 && s_last == FIN_BLOCKS - 1) {
        float s = 0.0f;
        #pragma unroll
        for (int i = 0; i < FIN_BLOCKS; i++) s += g_psum[i];   // fixed order: deterministic
        out[0] = s / (float)(B_*V_);
        g_done = 0;                        // reset for next graph replay
    }
}

extern "C" void kernel_launch(void* const* d_in, const int* in_sizes, int n_in,
                              void* d_out, int out_size)
{
    const float* proj = (const float*)d_in[0];
    const float* Amat = (const float*)d_in[1];
    if (n_in >= 2 && in_sizes[0] == C_*V_ && in_sizes[1] == B_*N_*C_) {
        const float* t = proj; proj = Amat; Amat = t;
    }

    cudaFuncSetAttribute(gemm_cf_tc, cudaFuncAttributeMaxDynamicSharedMemorySize, SMEM_DYN);

    prep_B<<<dim3(C_/32, V_/32), dim3(32, 8)>>>(Amat);
    gemm_cf_tc<<<dim3(NRB, NCB), 256, SMEM_DYN>>>(proj);
    finalize1<<<FIN_BLOCKS, 256>>>((float*)d_out);
}

// round 16
// speedup vs baseline: 1.0164x; 1.0164x over previous
#include <cuda_runtime.h>
#include <cuda_fp16.h>
#include <cstdint>

// Problem constants
#define B_  8
#define N_  1024
#define C_  1024
#define V_  256
#define NK  16        // harmonics 1..16 (k=0 contributes exactly 0)

// Tiling: 128x64 CTA tile, BK=128, 2-stage, 1-pass fp16 MMA (R13 base)
#define TM  128
#define TN  64
#define BK  128
#define NCHUNK (C_/BK)     // 8
#define NRB (B_*N_/TM)     // 64 row blocks
#define NCB (V_/TN)        // 4 col blocks -> grid 256 CTAs, occ 2 -> one wave

// Padded SMEM rows: 128 fp16 = 256B + 16B pad (272 mod 128 = 16 -> conflict-free ldmatrix)
#define LDS_ROW 272
#define A_MAT (TM * LDS_ROW)           // 34816
#define B_MAT (TN * LDS_ROW)           // 17408
#define OFF_A  0
#define OFF_B  (A_MAT)
#define STAGE_BYTES (A_MAT + B_MAT)    // 52224
#define XS_LD 68
#define SMEM_DYN (2*STAGE_BYTES)       // 104448 -> 2 CTAs/SM

// prep grid split (exact R11/R13 shape: measured 9.76-9.95us)
#define PROJ_BLOCKS 2048               // 4 float4 per thread
#define PREP_BLOCKS (PROJ_BLOCKS + 256)

#define FIN_BLOCKS 64

typedef unsigned long long u64;

__device__ __half g_projh[(size_t)B_*N_*C_];     // proj in fp16 (rounded once)
__device__ __half g_Bt[(size_t)V_*C_];           // A^T in fp16: [v][c]
__device__ float g_part[NRB][V_][2*NK];
__device__ float g_psum[FIN_BLOCKS];
__device__ unsigned int g_done;   // zero-init; reset by last block each run

// ---------------- helpers ----------------
__device__ __forceinline__ uint32_t smem_u32(const void* p) {
    uint32_t a;
    asm("{ .reg .u64 t; cvta.to.shared.u64 t, %1; cvt.u32.u64 %0, t; }" : "=r"(a) : "l"(p));
    return a;
}

__device__ __forceinline__ void ldsm4(uint32_t* r, uint32_t addr) {
    asm volatile("ldmatrix.sync.aligned.m8n8.x4.shared.b16 {%0,%1,%2,%3}, [%4];"
        : "=r"(r[0]), "=r"(r[1]), "=r"(r[2]), "=r"(r[3]) : "r"(addr));
}

__device__ __forceinline__ void mma_f16(float* c, const uint32_t* a, const uint32_t* b) {
    asm volatile(
        "mma.sync.aligned.m16n8k16.row.col.f32.f16.f16.f32 "
        "{%0,%1,%2,%3}, {%4,%5,%6,%7}, {%8,%9}, {%0,%1,%2,%3};"
        : "+f"(c[0]), "+f"(c[1]), "+f"(c[2]), "+f"(c[3])
        : "r"(a[0]), "r"(a[1]), "r"(a[2]), "r"(a[3]), "r"(b[0]), "r"(b[1]));
}

__device__ __forceinline__ void cp_async16(uint32_t dst, const void* src) {
    asm volatile("cp.async.cg.shared.global [%0], [%1], 16;" :: "r"(dst), "l"(src));
}
#define CP_COMMIT() asm volatile("cp.async.commit_group;" ::: "memory")
#define CP_WAIT0()  asm volatile("cp.async.wait_group 0;" ::: "memory")

// ---- packed f32x2 (PTX ISA 8.6, base sm_100) ----
__device__ __forceinline__ u64 pack2(float lo, float hi) {
    u64 r; asm("mov.b64 %0, {%1, %2};" : "=l"(r) : "f"(lo), "f"(hi)); return r;
}
__device__ __forceinline__ void unpack2(u64 v, float& lo, float& hi) {
    asm("mov.b64 {%0, %1}, %2;" : "=f"(lo), "=f"(hi) : "l"(v));
}
__device__ __forceinline__ u64 fma2(u64 a, u64 b, u64 c) {
    u64 d; asm("fma.rn.f32x2 %0, %1, %2, %3;" : "=l"(d) : "l"(a), "l"(b), "l"(c)); return d;
}
__device__ __forceinline__ u64 add2(u64 a, u64 b) {
    u64 d; asm("add.rn.f32x2 %0, %1, %2;" : "=l"(d) : "l"(a), "l"(b)); return d;
}
__device__ __forceinline__ u64 neg2(u64 a) {   // sub from +0: ptxas folds into FFMA neg-c
    u64 d; asm("sub.rn.f32x2 %0, %1, %2;" : "=l"(d) : "l"(0ULL), "l"(a)); return d;
}

// ---------------- merged prep kernel (exact R13 version) ----------------
__global__ void prep_all(const float* __restrict__ proj, const float* __restrict__ Amat)
{
    if (blockIdx.x < PROJ_BLOCKS) {
        const size_t base = (size_t)blockIdx.x * 1024 + threadIdx.x;
        #pragma unroll
        for (int j = 0; j < 4; j++) {
            const size_t i = base + 256 * j;   // float4 index
            float4 a = ((const float4*)proj)[i];
            __half2 h01 = __floats2half2_rn(a.x, a.y);
            __half2 h23 = __floats2half2_rn(a.z, a.w);
            ((uint2*)g_projh)[i] = make_uint2(*(uint32_t*)&h01, *(uint32_t*)&h23);
        }
    } else {
        __shared__ float sh[32][33];
        const int blk = blockIdx.x - PROJ_BLOCKS;       // 0..255
        const int c0 = (blk & 31) * 32, v0 = (blk >> 5) * 32;
        const int tx = threadIdx.x & 31, ty = threadIdx.x >> 5;   // 32 x 8
        #pragma unroll
        for (int j = 0; j < 4; j++)
            sh[ty + 8*j][tx] = Amat[(size_t)(c0 + ty + 8*j) * V_ + v0 + tx];
        __syncthreads();
        #pragma unroll
        for (int j = 0; j < 4; j++) {
            const int v = v0 + ty + 8*j, c = c0 + tx;
            g_Bt[(size_t)v * C_ + c] = __float2half_rn(sh[tx][ty + 8*j]);
        }
    }
}

// ---------------- staging: all cp.async (BK=128) ----------------
__device__ __forceinline__ void stage_async(uint32_t sg, int row0, int col0, int ch, int t)
{
    #pragma unroll
    for (int j = 0; j < 8; j++) {
        const int i = t + 256 * j;
        const int row = i >> 4, kq = i & 15;
        const size_t g = (size_t)(row0 + row) * C_ + ch * BK + kq * 8;
        cp_async16(sg + OFF_A + (uint32_t)(row * LDS_ROW + kq * 16), g_projh + g);
    }
    #pragma unroll
    for (int j = 0; j < 4; j++) {
        const int i = t + 256 * j;
        const int row = i >> 4, kq = i & 15;
        const size_t g = (size_t)(col0 + row) * C_ + ch * BK + kq * 8;
        cp_async16(sg + OFF_B + (uint32_t)(row * LDS_ROW + kq * 16), g_Bt + g);
    }
    CP_COMMIT();
}

// ---------------- main fused kernel ----------------
__global__ void __launch_bounds__(256, 2) gemm_cf_tc()
{
    extern __shared__ char smem[];
    const uint32_t sbase = smem_u32(smem);

    const int tid  = threadIdx.x;
    const int wid  = tid >> 5;
    const int lane = tid & 31;
    const int rb   = blockIdx.x;            // 0..63
    const int cb   = blockIdx.y;            // 0..3
    const int row0 = rb * TM;
    const int col0 = cb * TN;

    // warp grid 4(M) x 2(N): warp tile 32x32
    const int wm0 = (wid >> 1) * 32;
    const int wn0 = (wid & 1) * 32;

    // per-lane ldmatrix address components
    const int sub = lane >> 3, r8 = lane & 7;
    const int a_m = r8 + (sub & 1) * 8;
    const int a_k = (sub >> 1) * 8;
    const int b_n = r8 + (sub >> 1) * 8;
    const int b_k = (sub & 1) * 8;

    float acc[2][4][4];
    #pragma unroll
    for (int mt = 0; mt < 2; mt++)
        #pragma unroll
        for (int nt = 0; nt < 4; nt++)
            #pragma unroll
            for (int j = 0; j < 4; j++) acc[mt][nt][j] = 0.0f;

    // prologue: fill stage 0
    stage_async(sbase, row0, col0, 0, tid);
    CP_WAIT0();
    __syncthreads();

    for (int ch = 0; ch < NCHUNK; ch++) {
        const uint32_t sg = sbase + (ch & 1) * STAGE_BYTES;
        const uint32_t sn = sbase + ((ch + 1) & 1) * STAGE_BYTES;
        const bool more = (ch + 1 < NCHUNK);

        if (more)
            stage_async(sn, row0, col0, ch + 1, tid);   // async fill of next buffer

        // compute on current stage: 8 k-steps
        #pragma unroll
        for (int ks = 0; ks < 8; ks++) {
            const int k0 = ks * 16;
            uint32_t fb[4][2];
            #pragma unroll
            for (int ng = 0; ng < 2; ng++) {
                uint32_t tmp[4];
                const uint32_t baddr = sg + (uint32_t)(OFF_B + (wn0 + ng*16 + b_n) * LDS_ROW + (k0 + b_k) * 2);
                ldsm4(tmp, baddr);
                fb[2*ng][0] = tmp[0]; fb[2*ng][1] = tmp[1];
                fb[2*ng+1][0] = tmp[2]; fb[2*ng+1][1] = tmp[3];
            }
            #pragma unroll
            for (int mt = 0; mt < 2; mt++) {
                uint32_t fa[4];
                const uint32_t aaddr = sg + (uint32_t)(OFF_A + (wm0 + mt*16 + a_m) * LDS_ROW + (k0 + a_k) * 2);
                ldsm4(fa, aaddr);
                #pragma unroll
                for (int nt = 0; nt < 4; nt++)
                    mma_f16(acc[mt][nt], fa, fb[nt]);
            }
        }

        if (more) {
            CP_WAIT0();
            __syncthreads();         // single barrier per chunk
        }
    }

    // ---- epilogue: accumulators -> xs[128][XS_LD] ----
    __syncthreads();   // all MMA reads of final stage done before smem reuse
    float* xs = (float*)smem;
    {
        const int mrow = lane >> 2;
        const int ncol = 2 * (lane & 3);
        #pragma unroll
        for (int mt = 0; mt < 2; mt++)
            #pragma unroll
            for (int nt = 0; nt < 4; nt++) {
                const int m = wm0 + mt*16 + mrow;
                const int n = wn0 + nt*8 + ncol;
                *(float2*)&xs[(size_t)m * XS_LD + n]       = make_float2(acc[mt][nt][0], acc[mt][nt][1]);
                *(float2*)&xs[(size_t)(m + 8) * XS_LD + n] = make_float2(acc[mt][nt][2], acc[mt][nt][3]);
            }
    }
    __syncthreads();

    // ---- trig phase (packed f32x2): 4 lanes per column, 32 rows each ----
    const int col = tid >> 2;      // 0..63
    const int q   = tid & 3;       // row quarter
    const float dt = 3.0f / 16.0f;
    u64 pacc[NK];
    #pragma unroll
    for (int k = 0; k < NK; k++) pacc[k] = 0ULL;   // {+0,+0}

    #pragma unroll 4
    for (int i = 0; i < 32; i++) {
        float x = xs[(size_t)(q * 32 + i) * XS_LD + col];
        float s1, c1;
        __sincosf(x * dt, &s1, &c1);
        u64 tc2  = pack2(2.0f * c1, 2.0f * c1);
        u64 csk  = pack2(c1, s1);            // cs_1
        u64 ncskm = pack2(-1.0f, 0.0f);      // -cs_0 = {-1, -0}
        pacc[0] = add2(pacc[0], csk);
        #pragma unroll
        for (int k = 1; k < NK; k++) {
            u64 csn = fma2(tc2, csk, ncskm); // cs_{k+1} = tc*cs_k - cs_{k-1}
            ncskm = neg2(csk);               // folds into next fma's neg-c
            csk = csn;
            pacc[k] = add2(pacc[k], csn);
        }
    }

    // reduce across the 4 lanes sharing this column
    #pragma unroll
    for (int k = 0; k < NK; k++) {
        pacc[k] = add2(pacc[k], __shfl_xor_sync(0xffffffffu, pacc[k], 1));
        pacc[k] = add2(pacc[k], __shfl_xor_sync(0xffffffffu, pacc[k], 2));
    }
    if (q == 0) {
        u64* dst = (u64*)&g_part[rb][col0 + col][0];   // layout: (cos_k, sin_k) pairs
        #pragma unroll
        for (int k = 0; k < NK; k++)
            dst[k] = pacc[k];
    }
}

// ---------------- finalize: 64 blocks; 8 lanes per (b,v) cell ----------------
__global__ void finalize1(float* out)
{
    const int b  = blockIdx.x >> 3;
    const int vg = blockIdx.x & 7;
    const int vl = threadIdx.x >> 3;     // 0..31 (v within group)
    const int m  = threadIdx.x & 7;      // float4 column owner (harmonics 2m, 2m+1)
    const int v  = vg * 32 + vl;

    float4 u = make_float4(0.f, 0.f, 0.f, 0.f);
    #pragma unroll
    for (int j = 0; j < 8; j++) {
        float4 p = *(const float4*)&g_part[b*8 + j][v][m*4];
        u.x += p.x; u.y += p.y; u.z += p.z; u.w += p.w;
    }

    const float dt = 3.0f / 16.0f;
    const float invN = 1.0f / (float)N_;
    float stat = 0.0f;
    {
        int k = 2*m;
        float t = (float)(k + 1) * dt;
        float phi = expf(-0.5f * t * t);
        float w = ((k == NK - 1) ? 1.0f : 2.0f) * dt * phi;
        float cm = u.x * invN, sm = u.y * invN;
        float d = cm - phi;
        stat += (d*d + sm*sm) * w;
        k = 2*m + 1;
        t = (float)(k + 1) * dt;
        phi = expf(-0.5f * t * t);
        w = ((k == NK - 1) ? 1.0f : 2.0f) * dt * phi;
        cm = u.z * invN; sm = u.w * invN;
        d = cm - phi;
        stat += (d*d + sm*sm) * w;
    }
    stat *= (float)N_;

    stat += __shfl_xor_sync(0xffffffffu, stat, 1);
    stat += __shfl_xor_sync(0xffffffffu, stat, 2);
    stat += __shfl_xor_sync(0xffffffffu, stat, 4);

    __shared__ float sh[32];
    __shared__ unsigned int s_last;
    if (m == 0) sh[vl] = stat;
    __syncthreads();

    if (threadIdx.x == 0) {
        float s = 0.0f;
        #pragma unroll
        for (int i = 0; i < 32; i++) s += sh[i];     // fixed order
        g_psum[blockIdx.x] = s;
        __threadfence();
        s_last = atomicAdd(&g_done, 1u);
    }
    __syncthreads();
    if (threadIdx.x == 0 && s_last == FIN_BLOCKS - 1) {
        float s = 0.0f;
        #pragma unroll
        for (int i = 0; i < FIN_BLOCKS; i++) s += g_psum[i];   // fixed order: deterministic
        out[0] = s / (float)(B_*V_);
        g_done = 0;                        // reset for next graph replay
    }
}

extern "C" void kernel_launch(void* const* d_in, const int* in_sizes, int n_in,
                              void* d_out, int out_size)
{
    const float* proj = (const float*)d_in[0];
    const float* Amat = (const float*)d_in[1];
    if (n_in >= 2 && in_sizes[0] == C_*V_ && in_sizes[1] == B_*N_*C_) {
        const float* t = proj; proj = Amat; Amat = t;
    }

    cudaFuncSetAttribute(gemm_cf_tc, cudaFuncAttributeMaxDynamicSharedMemorySize, SMEM_DYN);

    prep_all<<<PREP_BLOCKS, 256>>>(proj, Amat);
    gemm_cf_tc<<<dim3(NRB, NCB), 256, SMEM_DYN>>>();
    finalize1<<<FIN_BLOCKS, 256>>>((float*)d_out);
}

// round 17
// speedup vs baseline: 1.0172x; 1.0008x over previous
#include <cuda_runtime.h>
#include <cuda_fp16.h>
#include <cstdint>

// Problem constants
#define B_  8
#define N_  1024
#define C_  1024
#define V_  256
#define NK  16        // harmonics 1..16 (k=0 contributes exactly 0)

// Tiling: 128x64 CTA tile, BK=128, 2-stage, 1-pass fp16 MMA (R13/R16 base)
#define TM  128
#define TN  64
#define BK  128
#define NCHUNK (C_/BK)     // 8
#define NRB (B_*N_/TM)     // 64 row blocks
#define NCB (V_/TN)        // 4 col blocks -> grid 256 CTAs, occ 2 -> one wave

// Padded SMEM rows: 128 fp16 = 256B + 16B pad (272 mod 128 = 16 -> conflict-free ldmatrix)
#define LDS_ROW 272
#define A_MAT (TM * LDS_ROW)           // 34816
#define B_MAT (TN * LDS_ROW)           // 17408
#define OFF_A  0
#define OFF_B  (A_MAT)
#define STAGE_BYTES (A_MAT + B_MAT)    // 52224
#define XS_LD 68
#define SMEM_DYN (2*STAGE_BYTES)       // 104448 -> 2 CTAs/SM

// prep: single resident wave, MLP=8 loads, STG.128 stores
#define PROJ_BLOCKS 1024               // 256 thr x 8 float4 loads -> 4 uint4 stores
#define PREP_BLOCKS (PROJ_BLOCKS + 256)

#define FIN_BLOCKS 64

typedef unsigned long long u64;

__device__ __half g_projh[(size_t)B_*N_*C_];     // proj in fp16 (rounded once)
__device__ __half g_Bt[(size_t)V_*C_];           // A^T in fp16: [v][c]
__device__ float g_part[NRB][V_][2*NK];
__device__ float g_psum[FIN_BLOCKS];
__device__ unsigned int g_done;   // zero-init; reset by last block each run

// ---------------- helpers ----------------
__device__ __forceinline__ uint32_t smem_u32(const void* p) {
    uint32_t a;
    asm("{ .reg .u64 t; cvta.to.shared.u64 t, %1; cvt.u32.u64 %0, t; }" : "=r"(a) : "l"(p));
    return a;
}

__device__ __forceinline__ void ldsm4(uint32_t* r, uint32_t addr) {
    asm volatile("ldmatrix.sync.aligned.m8n8.x4.shared.b16 {%0,%1,%2,%3}, [%4];"
        : "=r"(r[0]), "=r"(r[1]), "=r"(r[2]), "=r"(r[3]) : "r"(addr));
}

__device__ __forceinline__ void mma_f16(float* c, const uint32_t* a, const uint32_t* b) {
    asm volatile(
        "mma.sync.aligned.m16n8k16.row.col.f32.f16.f16.f32 "
        "{%0,%1,%2,%3}, {%4,%5,%6,%7}, {%8,%9}, {%0,%1,%2,%3};"
        : "+f"(c[0]), "+f"(c[1]), "+f"(c[2]), "+f"(c[3])
        : "r"(a[0]), "r"(a[1]), "r"(a[2]), "r"(a[3]), "r"(b[0]), "r"(b[1]));
}

__device__ __forceinline__ void cp_async16(uint32_t dst, const void* src) {
    asm volatile("cp.async.cg.shared.global [%0], [%1], 16;" :: "r"(dst), "l"(src));
}
#define CP_COMMIT() asm volatile("cp.async.commit_group;" ::: "memory")
#define CP_WAIT0()  asm volatile("cp.async.wait_group 0;" ::: "memory")

// ---- packed f32x2 (PTX ISA 8.6, base sm_100) ----
__device__ __forceinline__ u64 pack2(float lo, float hi) {
    u64 r; asm("mov.b64 %0, {%1, %2};" : "=l"(r) : "f"(lo), "f"(hi)); return r;
}
__device__ __forceinline__ u64 fma2(u64 a, u64 b, u64 c) {
    u64 d; asm("fma.rn.f32x2 %0, %1, %2, %3;" : "=l"(d) : "l"(a), "l"(b), "l"(c)); return d;
}
__device__ __forceinline__ u64 add2(u64 a, u64 b) {
    u64 d; asm("add.rn.f32x2 %0, %1, %2;" : "=l"(d) : "l"(a), "l"(b)); return d;
}
__device__ __forceinline__ u64 neg2(u64 a) {   // sub from +0: ptxas folds into FFMA neg-c
    u64 d; asm("sub.rn.f32x2 %0, %1, %2;" : "=l"(d) : "l"(0ULL), "l"(a)); return d;
}

// ---------------- merged prep kernel ----------------
// blocks [0, PROJ_BLOCKS): proj fp32 -> fp16.
//   Per thread: 8 float4 loads (4 consecutive pairs, all hoisted -> MLP=8),
//   then 4 uint4 (STG.128) stores, stride-1 coalesced.
// blocks [PROJ_BLOCKS, PREP_BLOCKS): transpose A (C,V) -> Bt (V,C) fp16
__global__ void prep_all(const float* __restrict__ proj, const float* __restrict__ Amat)
{
    if (blockIdx.x < PROJ_BLOCKS) {
        const float4* p4 = (const float4*)proj;
        uint4* o4 = (uint4*)g_projh;
        const size_t t2 = (size_t)blockIdx.x * 2048 + threadIdx.x * 2;

        float4 a[8];
        #pragma unroll
        for (int j = 0; j < 4; j++) {
            a[2*j]   = p4[t2 + 512*j];
            a[2*j+1] = p4[t2 + 512*j + 1];
        }
        #pragma unroll
        for (int j = 0; j < 4; j++) {
            __half2 h0 = __floats2half2_rn(a[2*j].x,   a[2*j].y);
            __half2 h1 = __floats2half2_rn(a[2*j].z,   a[2*j].w);
            __half2 h2 = __floats2half2_rn(a[2*j+1].x, a[2*j+1].y);
            __half2 h3 = __floats2half2_rn(a[2*j+1].z, a[2*j+1].w);
            o4[(t2 >> 1) + 256*j] = make_uint4(*(uint32_t*)&h0, *(uint32_t*)&h1,
                                               *(uint32_t*)&h2, *(uint32_t*)&h3);
        }
    } else {
        __shared__ float sh[32][33];
        const int blk = blockIdx.x - PROJ_BLOCKS;       // 0..255
        const int c0 = (blk & 31) * 32, v0 = (blk >> 5) * 32;
        const int tx = threadIdx.x & 31, ty = threadIdx.x >> 5;   // 32 x 8
        #pragma unroll
        for (int j = 0; j < 4; j++)
            sh[ty + 8*j][tx] = Amat[(size_t)(c0 + ty + 8*j) * V_ + v0 + tx];
        __syncthreads();
        #pragma unroll
        for (int j = 0; j < 4; j++) {
            const int v = v0 + ty + 8*j, c = c0 + tx;
            g_Bt[(size_t)v * C_ + c] = __float2half_rn(sh[tx][ty + 8*j]);
        }
    }
}

// ---------------- staging: all cp.async (BK=128) ----------------
__device__ __forceinline__ void stage_async(uint32_t sg, int row0, int col0, int ch, int t)
{
    #pragma unroll
    for (int j = 0; j < 8; j++) {
        const int i = t + 256 * j;
        const int row = i >> 4, kq = i & 15;
        const size_t g = (size_t)(row0 + row) * C_ + ch * BK + kq * 8;
        cp_async16(sg + OFF_A + (uint32_t)(row * LDS_ROW + kq * 16), g_projh + g);
    }
    #pragma unroll
    for (int j = 0; j < 4; j++) {
        const int i = t + 256 * j;
        const int row = i >> 4, kq = i & 15;
        const size_t g = (size_t)(col0 + row) * C_ + ch * BK + kq * 8;
        cp_async16(sg + OFF_B + (uint32_t)(row * LDS_ROW + kq * 16), g_Bt + g);
    }
    CP_COMMIT();
}

// ---------------- main fused kernel ----------------
__global__ void __launch_bounds__(256, 2) gemm_cf_tc()
{
    extern __shared__ char smem[];
    const uint32_t sbase = smem_u32(smem);

    const int tid  = threadIdx.x;
    const int wid  = tid >> 5;
    const int lane = tid & 31;
    const int rb   = blockIdx.x;            // 0..63
    const int cb   = blockIdx.y;            // 0..3
    const int row0 = rb * TM;
    const int col0 = cb * TN;

    // warp grid 4(M) x 2(N): warp tile 32x32
    const int wm0 = (wid >> 1) * 32;
    const int wn0 = (wid & 1) * 32;

    // per-lane ldmatrix address components
    const int sub = lane >> 3, r8 = lane & 7;
    const int a_m = r8 + (sub & 1) * 8;
    const int a_k = (sub >> 1) * 8;
    const int b_n = r8 + (sub >> 1) * 8;
    const int b_k = (sub & 1) * 8;

    float acc[2][4][4];
    #pragma unroll
    for (int mt = 0; mt < 2; mt++)
        #pragma unroll
        for (int nt = 0; nt < 4; nt++)
            #pragma unroll
            for (int j = 0; j < 4; j++) acc[mt][nt][j] = 0.0f;

    // prologue: fill stage 0
    stage_async(sbase, row0, col0, 0, tid);
    CP_WAIT0();
    __syncthreads();

    for (int ch = 0; ch < NCHUNK; ch++) {
        const uint32_t sg = sbase + (ch & 1) * STAGE_BYTES;
        const uint32_t sn = sbase + ((ch + 1) & 1) * STAGE_BYTES;
        const bool more = (ch + 1 < NCHUNK);

        if (more)
            stage_async(sn, row0, col0, ch + 1, tid);   // async fill of next buffer

        // compute on current stage: 8 k-steps
        #pragma unroll
        for (int ks = 0; ks < 8; ks++) {
            const int k0 = ks * 16;
            uint32_t fb[4][2];
            #pragma unroll
            for (int ng = 0; ng < 2; ng++) {
                uint32_t tmp[4];
                const uint32_t baddr = sg + (uint32_t)(OFF_B + (wn0 + ng*16 + b_n) * LDS_ROW + (k0 + b_k) * 2);
                ldsm4(tmp, baddr);
                fb[2*ng][0] = tmp[0]; fb[2*ng][1] = tmp[1];
                fb[2*ng+1][0] = tmp[2]; fb[2*ng+1][1] = tmp[3];
            }
            #pragma unroll
            for (int mt = 0; mt < 2; mt++) {
                uint32_t fa[4];
                const uint32_t aaddr = sg + (uint32_t)(OFF_A + (wm0 + mt*16 + a_m) * LDS_ROW + (k0 + a_k) * 2);
                ldsm4(fa, aaddr);
                #pragma unroll
                for (int nt = 0; nt < 4; nt++)
                    mma_f16(acc[mt][nt], fa, fb[nt]);
            }
        }

        if (more) {
            CP_WAIT0();
            __syncthreads();         // single barrier per chunk
        }
    }

    // ---- epilogue: accumulators -> xs[128][XS_LD] ----
    __syncthreads();   // all MMA reads of final stage done before smem reuse
    float* xs = (float*)smem;
    {
        const int mrow = lane >> 2;
        const int ncol = 2 * (lane & 3);
        #pragma unroll
        for (int mt = 0; mt < 2; mt++)
            #pragma unroll
            for (int nt = 0; nt < 4; nt++) {
                const int m = wm0 + mt*16 + mrow;
                const int n = wn0 + nt*8 + ncol;
                *(float2*)&xs[(size_t)m * XS_LD + n]       = make_float2(acc[mt][nt][0], acc[mt][nt][1]);
                *(float2*)&xs[(size_t)(m + 8) * XS_LD + n] = make_float2(acc[mt][nt][2], acc[mt][nt][3]);
            }
    }
    __syncthreads();

    // ---- trig phase (packed f32x2): 4 lanes per column, 32 rows each ----
    const int col = tid >> 2;      // 0..63
    const int q   = tid & 3;       // row quarter
    const float dt = 3.0f / 16.0f;
    u64 pacc[NK];
    #pragma unroll
    for (int k = 0; k < NK; k++) pacc[k] = 0ULL;   // {+0,+0}

    #pragma unroll 4
    for (int i = 0; i < 32; i++) {
        float x = xs[(size_t)(q * 32 + i) * XS_LD + col];
        float s1, c1;
        __sincosf(x * dt, &s1, &c1);
        u64 tc2  = pack2(2.0f * c1, 2.0f * c1);
        u64 csk  = pack2(c1, s1);            // cs_1
        u64 ncskm = pack2(-1.0f, 0.0f);      // -cs_0 = {-1, -0}
        pacc[0] = add2(pacc[0], csk);
        #pragma unroll
        for (int k = 1; k < NK; k++) {
            u64 csn = fma2(tc2, csk, ncskm); // cs_{k+1} = tc*cs_k - cs_{k-1}
            ncskm = neg2(csk);               // folds into next fma's neg-c
            csk = csn;
            pacc[k] = add2(pacc[k], csn);
        }
    }

    // reduce across the 4 lanes sharing this column
    #pragma unroll
    for (int k = 0; k < NK; k++) {
        pacc[k] = add2(pacc[k], __shfl_xor_sync(0xffffffffu, pacc[k], 1));
        pacc[k] = add2(pacc[k], __shfl_xor_sync(0xffffffffu, pacc[k], 2));
    }
    if (q == 0) {
        u64* dst = (u64*)&g_part[rb][col0 + col][0];   // layout: (cos_k, sin_k) pairs
        #pragma unroll
        for (int k = 0; k < NK; k++)
            dst[k] = pacc[k];
    }
}

// ---------------- finalize: 64 blocks; 8 lanes per (b,v) cell ----------------
__global__ void finalize1(float* out)
{
    const int b  = blockIdx.x >> 3;
    const int vg = blockIdx.x & 7;
    const int vl = threadIdx.x >> 3;     // 0..31 (v within group)
    const int m  = threadIdx.x & 7;      // float4 column owner (harmonics 2m, 2m+1)
    const int v  = vg * 32 + vl;

    float4 u = make_float4(0.f, 0.f, 0.f, 0.f);
    #pragma unroll
    for (int j = 0; j < 8; j++) {
        float4 p = *(const float4*)&g_part[b*8 + j][v][m*4];
        u.x += p.x; u.y += p.y; u.z += p.z; u.w += p.w;
    }

    const float dt = 3.0f / 16.0f;
    const float invN = 1.0f / (float)N_;
    float stat = 0.0f;
    {
        int k = 2*m;
        float t = (float)(k + 1) * dt;
        float phi = expf(-0.5f * t * t);
        float w = ((k == NK - 1) ? 1.0f : 2.0f) * dt * phi;
        float cm = u.x * invN, sm = u.y * invN;
        float d = cm - phi;
        stat += (d*d + sm*sm) * w;
        k = 2*m + 1;
        t = (float)(k + 1) * dt;
        phi = expf(-0.5f * t * t);
        w = ((k == NK - 1) ? 1.0f : 2.0f) * dt * phi;
        cm = u.z * invN; sm = u.w * invN;
        d = cm - phi;
        stat += (d*d + sm*sm) * w;
    }
    stat *= (float)N_;

    stat += __shfl_xor_sync(0xffffffffu, stat, 1);
    stat += __shfl_xor_sync(0xffffffffu, stat, 2);
    stat += __shfl_xor_sync(0xffffffffu, stat, 4);

    __shared__ float sh[32];
    __shared__ unsigned int s_last;
    if (m == 0) sh[vl] = stat;
    __syncthreads();

    if (threadIdx.x == 0) {
        float s = 0.0f;
        #pragma unroll
        for (int i = 0; i < 32; i++) s += sh[i];     // fixed order
        g_psum[blockIdx.x] = s;
        __threadfence();
        s_last = atomicAdd(&g_done, 1u);
    }
    __syncthreads();
    if (threadIdx.x == 0 && s_last == FIN_BLOCKS - 1) {
        float s = 0.0f;
        #pragma unroll
        for (int i = 0; i < FIN_BLOCKS; i++) s += g_psum[i];   // fixed order: deterministic
        out[0] = s / (float)(B_*V_);
        g_done = 0;                        // reset for next graph replay
    }
}

extern "C" void kernel_launch(void* const* d_in, const int* in_sizes, int n_in,
                              void* d_out, int out_size)
{
    const float* proj = (const float*)d_in[0];
    const float* Amat = (const float*)d_in[1];
    if (n_in >= 2 && in_sizes[0] == C_*V_ && in_sizes[1] == B_*N_*C_) {
        const float* t = proj; proj = Amat; Amat = t;
    }

    cudaFuncSetAttribute(gemm_cf_tc, cudaFuncAttributeMaxDynamicSharedMemorySize, SMEM_DYN);

    prep_all<<<PREP_BLOCKS, 256>>>(proj, Amat);
    gemm_cf_tc<<<dim3(NRB, NCB), 256, SMEM_DYN>>>();
    finalize1<<<FIN_BLOCKS, 256>>>((float*)d_out);
}